// round 5
// baseline (speedup 1.0000x reference)
#include <cuda_runtime.h>
#include <cuda_fp16.h>
#include <float.h>
#include <stdint.h>

#define Bsz  8
#define Cdim 128
#define Ndim 4096
#define Odim 256
#define KNN  16

// ---------------- scratch (static device globals; no allocations) -------------
__device__ float g_net[Bsz * Cdim * Ndim];     // [b][c][n]      16 MB
__device__ float g_sq[Bsz * Ndim];             // [b][n]
__device__ int   g_idx[Bsz * Ndim * KNN];      // [b][n][k]       2 MB
__device__ float g_p1t[Bsz * Ndim * Odim];     // [b][n][o]      32 MB
__device__ float g_baset[Bsz * Ndim * Odim];   // [b][n][o]      32 MB
__device__ __half g_hi[Bsz * Ndim * Cdim];     // [b][n][c]       8 MB
__device__ __half g_lo[Bsz * Ndim * Cdim];     // [b][n][c]       8 MB

__device__ __forceinline__ uint32_t smem_u32(const void* p) {
    uint32_t a;
    asm("{ .reg .u64 t; cvta.to.shared.u64 t, %1; cvt.u32.u64 %0, t; }" : "=r"(a) : "l"(p));
    return a;
}
__device__ __forceinline__ void ldmx4(uint32_t* r, uint32_t addr) {
    asm volatile("ldmatrix.sync.aligned.m8n8.x4.shared.b16 {%0,%1,%2,%3}, [%4];"
        : "=r"(r[0]), "=r"(r[1]), "=r"(r[2]), "=r"(r[3]) : "r"(addr));
}
__device__ __forceinline__ void mma16816(float* c, const uint32_t* a,
                                         uint32_t b0, uint32_t b1) {
    asm volatile("mma.sync.aligned.m16n8k16.row.col.f32.f16.f16.f32 "
        "{%0,%1,%2,%3}, {%4,%5,%6,%7}, {%8,%9}, {%0,%1,%2,%3};"
        : "+f"(c[0]), "+f"(c[1]), "+f"(c[2]), "+f"(c[3])
        : "r"(a[0]), "r"(a[1]), "r"(a[2]), "r"(a[3]), "r"(b0), "r"(b1));
}

// ==============================================================================
// Kernel A: net = relu(w0 @ x + b0), fused sq[b][n] = sum_c net^2
// ==============================================================================
__global__ __launch_bounds__(256) void k_net(const float* __restrict__ x,
                                             const float* __restrict__ w0,
                                             const float* __restrict__ b0) {
    __shared__ float Ws[32][129];
    __shared__ float Ns[32][128];
    __shared__ float sqs[16][129];

    const int b  = blockIdx.y;
    const int n0 = blockIdx.x * 128;
    const int tid = threadIdx.x;
    const int tx = tid & 15;
    const int ty = tid >> 4;

    float acc[8][8];
    #pragma unroll
    for (int i = 0; i < 8; ++i)
        #pragma unroll
        for (int j = 0; j < 8; ++j) acc[i][j] = 0.f;

    for (int k0 = 0; k0 < 128; k0 += 32) {
        __syncthreads();
        #pragma unroll
        for (int i = 0; i < 16; ++i) {
            int idx = tid + i * 256;
            int cc = idx & 31, o = idx >> 5;
            Ws[cc][o] = w0[o * 128 + k0 + cc];
        }
        #pragma unroll
        for (int i = 0; i < 16; ++i) {
            int idx = tid + i * 256;
            int c = idx >> 7, n = idx & 127;
            Ns[c][n] = x[(b * 128 + k0 + c) * Ndim + n0 + n];
        }
        __syncthreads();
        #pragma unroll
        for (int kk = 0; kk < 32; ++kk) {
            float4 x0 = *(const float4*)&Ns[kk][tx * 8];
            float4 x1 = *(const float4*)&Ns[kk][tx * 8 + 4];
            float xr[8] = {x0.x, x0.y, x0.z, x0.w, x1.x, x1.y, x1.z, x1.w};
            #pragma unroll
            for (int i = 0; i < 8; ++i) {
                float wv = Ws[kk][ty * 8 + i];
                #pragma unroll
                for (int j = 0; j < 8; ++j) acc[i][j] += wv * xr[j];
            }
        }
    }

    float part[8];
    #pragma unroll
    for (int j = 0; j < 8; ++j) part[j] = 0.f;

    #pragma unroll
    for (int i = 0; i < 8; ++i) {
        int o = ty * 8 + i;
        float bv = __ldg(&b0[o]);
        float r[8];
        #pragma unroll
        for (int j = 0; j < 8; ++j) {
            r[j] = fmaxf(acc[i][j] + bv, 0.f);
            part[j] += r[j] * r[j];
        }
        int base = (b * 128 + o) * Ndim + n0 + tx * 8;
        float4 s0 = {r[0], r[1], r[2], r[3]};
        float4 s1 = {r[4], r[5], r[6], r[7]};
        *(float4*)&g_net[base]     = s0;
        *(float4*)&g_net[base + 4] = s1;
    }
    #pragma unroll
    for (int j = 0; j < 8; ++j) sqs[ty][tx * 8 + j] = part[j];
    __syncthreads();
    if (tid < 128) {
        float s = 0.f;
        #pragma unroll
        for (int r = 0; r < 16; ++r) s += sqs[r][tid];
        g_sq[b * Ndim + n0 + tid] = s;
    }
}

// ==============================================================================
// Kernel B: fp16 hi/lo split + transpose: g_net[b][c][n] -> g_hi/g_lo[b][n][c]
// ==============================================================================
__global__ __launch_bounds__(256) void k_split() {
    __shared__ float s[32][33];
    const int b  = blockIdx.z;
    const int c0 = blockIdx.y * 32;
    const int n0 = blockIdx.x * 32;
    const int tx = threadIdx.x & 31;
    const int ty = threadIdx.x >> 5;    // 0..7

    #pragma unroll
    for (int i = 0; i < 4; ++i) {
        int c = ty + i * 8;
        s[c][tx] = g_net[(b * Cdim + c0 + c) * Ndim + n0 + tx];
    }
    __syncthreads();
    #pragma unroll
    for (int i = 0; i < 4; ++i) {
        int nl = ty + i * 8;
        float v = s[tx][nl];
        __half hi = __float2half(v);
        __half lo = __float2half(v - __half2float(hi));
        int dst = (b * Ndim + n0 + nl) * Cdim + c0 + tx;
        g_hi[dst] = hi;
        g_lo[dst] = lo;
    }
}

// ==============================================================================
// Kernel C v4: kNN via mma.sync fp16 hi/lo-compensated gram.
// grid (32, 8), 256 threads (8 warps). Warp w: q rows [w*16, w*16+16).
// 3 passes (hi*hi + hi*lo + lo*hi), fp32 accum, keys -> smem -> top-17 scan.
// ==============================================================================
#define PITCHB 272                     // 136 halves/row: conflict-free ldmatrix
#define TILEB  (128 * PITCHB)          // 34816 B per 128x128 fp16 tile
#define SM_QHI 0
#define SM_QLO TILEB
#define SM_MHI (2 * TILEB)
#define SM_MLO (3 * TILEB)
#define SM_KEY (4 * TILEB)             // 128 x 132 floats = 67584 B
#define SM_SQM (SM_KEY + 128 * 132 * 4)
#define SM_TOT (SM_SQM + 512)

__device__ __forceinline__ void load_tile16(char* smem, uint32_t dst,
                                            const __half* __restrict__ src) {
    for (int i = threadIdx.x; i < 2048; i += 256) {
        int row = i >> 4, c8 = (i & 15) * 8;
        uint4 v = *(const uint4*)(src + row * Cdim + c8);
        *(uint4*)(smem + dst + row * PITCHB + c8 * 2) = v;
    }
}

__device__ __forceinline__ void topk_insert(float* kd, int* ki, float d, int m) {
    int j = 16;
    #pragma unroll 1
    while (j > 0 && kd[j - 1] > d) { kd[j] = kd[j - 1]; ki[j] = ki[j - 1]; --j; }
    kd[j] = d; ki[j] = m;
}

__global__ __launch_bounds__(256) void k_knn() {
    extern __shared__ char smem[];
    const uint32_t sbase = smem_u32(smem);
    const int tid  = threadIdx.x;
    const int lane = tid & 31;
    const int wid  = tid >> 5;          // 0..7
    const int b    = blockIdx.y;
    const int n0   = blockIdx.x * 128;
    const int qbase = wid * 16;

    // Stage Q hi/lo once
    load_tile16(smem, SM_QHI, g_hi + (size_t)(b * Ndim + n0) * Cdim);
    load_tile16(smem, SM_QLO, g_lo + (size_t)(b * Ndim + n0) * Cdim);

    // ldmatrix base addresses (A: 16x16 row-major; B: [n][k] for col-major k x n)
    const uint32_t a_base = sbase + (qbase + (lane & 15)) * PITCHB + ((lane >> 4) << 4);
    const uint32_t b_base = sbase + ((lane & 7) + ((lane >> 4) << 3)) * PITCHB
                                  + (((lane >> 3) & 1) << 4);

    float* keysp = (float*)(smem + SM_KEY);
    const float* sqm = (const float*)(smem + SM_SQM);

    float kd[17]; int ki[17];
    #pragma unroll
    for (int i = 0; i < 17; ++i) { kd[i] = FLT_MAX; ki[i] = 0; }
    float worst = FLT_MAX;

    for (int mt = 0; mt < 32; ++mt) {
        const int m0 = mt * 128;
        __syncthreads();   // previous scan done; M tiles reusable
        load_tile16(smem, SM_MHI, g_hi + (size_t)(b * Ndim + m0) * Cdim);
        load_tile16(smem, SM_MLO, g_lo + (size_t)(b * Ndim + m0) * Cdim);
        if (tid < 128) ((float*)(smem + SM_SQM))[tid] = g_sq[b * Ndim + m0 + tid];
        __syncthreads();

        float c[16][4];
        #pragma unroll
        for (int t = 0; t < 16; ++t)
            #pragma unroll
            for (int e = 0; e < 4; ++e) c[t][e] = 0.f;

        #pragma unroll 1
        for (int pass = 0; pass < 3; ++pass) {
            const uint32_t abase = a_base + (pass == 2 ? SM_QLO : SM_QHI);
            const uint32_t bbase = b_base + (pass == 1 ? SM_MLO : SM_MHI);
            #pragma unroll
            for (int ks = 0; ks < 8; ++ks) {
                uint32_t ra[4];
                ldmx4(ra, abase + ks * 32);
                #pragma unroll
                for (int tp = 0; tp < 8; ++tp) {
                    uint32_t rb[4];
                    ldmx4(rb, bbase + tp * (16 * PITCHB) + ks * 32);
                    mma16816(c[2 * tp],     ra, rb[0], rb[1]);
                    mma16816(c[2 * tp + 1], ra, rb[2], rb[3]);
                }
            }
        }

        // keys[q][m] = sq[m] - 2*dot   (C frag: q = qbase + lane/4 (+8), m = 8t + (lane%4)*2 (+1))
        const int q0 = qbase + (lane >> 2);
        const int mo = (lane & 3) * 2;
        #pragma unroll
        for (int t = 0; t < 16; ++t) {
            int m = t * 8 + mo;
            float s0 = sqm[m], s1 = sqm[m + 1];
            *(float2*)&keysp[q0 * 132 + m] =
                make_float2(s0 - 2.f * c[t][0], s1 - 2.f * c[t][1]);
            *(float2*)&keysp[(q0 + 8) * 132 + m] =
                make_float2(s0 - 2.f * c[t][2], s1 - 2.f * c[t][3]);
        }
        __syncthreads();

        // streaming top-17 scan (threads 0..127, one query each)
        if (tid < 128) {
            const float* krow = keysp + tid * 132;
            #pragma unroll 4
            for (int m = 0; m < 128; ++m) {
                float kv = krow[m];
                if (kv < worst) { topk_insert(kd, ki, kv, m0 + m); worst = kd[16]; }
            }
        }
    }

    if (tid < 128) {
        const int q = n0 + tid;
        #pragma unroll
        for (int t = 0; t < 16; ++t)
            g_idx[(b * Ndim + q) * KNN + t] = ki[t + 1];   // drop self (strict min)
    }
}

// ==============================================================================
// Kernel D: p1 = w1@net ; base = w2@net + b1 + b2 - p1 ; both stored [b][n][o]
// ==============================================================================
__global__ __launch_bounds__(256) void k_proj(const float* __restrict__ w1,
                                              const float* __restrict__ b1,
                                              const float* __restrict__ w2,
                                              const float* __restrict__ b2) {
    __shared__ float W1c[16][129];
    __shared__ float W2c[16][129];
    __shared__ float Ns[16][128];

    const int b  = blockIdx.y;
    const int n0 = blockIdx.x * 128;
    const int oz = blockIdx.z * 128;
    const int tid = threadIdx.x;
    const int tx = tid & 15;
    const int ty = tid >> 4;

    float a1[8][8], a2[8][8];
    #pragma unroll
    for (int j = 0; j < 8; ++j)
        #pragma unroll
        for (int i = 0; i < 8; ++i) { a1[j][i] = 0.f; a2[j][i] = 0.f; }

    for (int k0 = 0; k0 < 128; k0 += 16) {
        __syncthreads();
        #pragma unroll
        for (int i = 0; i < 8; ++i) {
            int idx = tid + i * 256;
            int cc = idx & 15, o = idx >> 4;
            W1c[cc][o] = w1[(oz + o) * 128 + k0 + cc];
            W2c[cc][o] = w2[(oz + o) * 128 + k0 + cc];
        }
        #pragma unroll
        for (int i = 0; i < 8; ++i) {
            int idx = tid + i * 256;
            int c = idx >> 7, n = idx & 127;
            Ns[c][n] = g_net[(b * 128 + k0 + c) * Ndim + n0 + n];
        }
        __syncthreads();
        #pragma unroll
        for (int kk = 0; kk < 16; ++kk) {
            float4 nv0 = *(const float4*)&Ns[kk][ty * 8];
            float4 nv1 = *(const float4*)&Ns[kk][ty * 8 + 4];
            float nr[8] = {nv0.x, nv0.y, nv0.z, nv0.w, nv1.x, nv1.y, nv1.z, nv1.w};
            float w1r[8], w2r[8];
            #pragma unroll
            for (int i = 0; i < 8; ++i) {
                w1r[i] = W1c[kk][tx * 8 + i];
                w2r[i] = W2c[kk][tx * 8 + i];
            }
            #pragma unroll
            for (int j = 0; j < 8; ++j)
                #pragma unroll
                for (int i = 0; i < 8; ++i) {
                    a1[j][i] += nr[j] * w1r[i];
                    a2[j][i] += nr[j] * w2r[i];
                }
        }
    }

    float bb[8];
    #pragma unroll
    for (int i = 0; i < 8; ++i) {
        int o = oz + tx * 8 + i;
        bb[i] = __ldg(&b1[o]) + __ldg(&b2[o]);
    }
    #pragma unroll
    for (int j = 0; j < 8; ++j) {
        int n = n0 + ty * 8 + j;
        int base = (b * Ndim + n) * Odim + oz + tx * 8;
        float4 p0  = {a1[j][0], a1[j][1], a1[j][2], a1[j][3]};
        float4 p1v = {a1[j][4], a1[j][5], a1[j][6], a1[j][7]};
        *(float4*)&g_p1t[base]     = p0;
        *(float4*)&g_p1t[base + 4] = p1v;
        float4 e0 = {a2[j][0] + bb[0] - a1[j][0], a2[j][1] + bb[1] - a1[j][1],
                     a2[j][2] + bb[2] - a1[j][2], a2[j][3] + bb[3] - a1[j][3]};
        float4 e1 = {a2[j][4] + bb[4] - a1[j][4], a2[j][5] + bb[5] - a1[j][5],
                     a2[j][6] + bb[6] - a1[j][6], a2[j][7] + bb[7] - a1[j][7]};
        *(float4*)&g_baset[base]     = e0;
        *(float4*)&g_baset[base + 4] = e1;
    }
}

// ==============================================================================
// Kernel E: y[b,o,n] = relu(max_k (base[b,n,o] + p1t[b,idx[n,k],o]))
// ==============================================================================
__global__ __launch_bounds__(256) void k_edge(float* __restrict__ out) {
    __shared__ int   idxs[32][16];
    __shared__ float ys[32][257];

    const int b  = blockIdx.y;
    const int n0 = blockIdx.x * 32;
    const int tid = threadIdx.x;

    #pragma unroll
    for (int i = 0; i < 2; ++i) {
        int j = tid + i * 256;
        idxs[j >> 4][j & 15] = g_idx[(b * Ndim + n0 + (j >> 4)) * KNN + (j & 15)];
    }
    __syncthreads();

    #pragma unroll 1
    for (int nn = 0; nn < 32; ++nn) {
        float v = g_baset[(b * Ndim + n0 + nn) * Odim + tid];
        float acc = -FLT_MAX;
        #pragma unroll
        for (int t = 0; t < 16; ++t) {
            int m = idxs[nn][t];
            acc = fmaxf(acc, v + g_p1t[(b * Ndim + m) * Odim + tid]);
        }
        ys[nn][tid] = fmaxf(acc, 0.f);
    }
    __syncthreads();

    #pragma unroll
    for (int i = 0; i < 32; ++i) {
        int j = tid + i * 256;
        int o = j >> 5, n = j & 31;
        out[(b * Odim + o) * Ndim + n0 + n] = ys[n][o];
    }
}

// ==============================================================================
extern "C" void kernel_launch(void* const* d_in, const int* in_sizes, int n_in,
                              void* d_out, int out_size) {
    const float *x = 0, *w0 = 0, *b0 = 0, *w1 = 0, *b1 = 0, *w2 = 0, *b2 = 0;
    for (int i = 0; i < n_in; ++i) {
        const float* p = (const float*)d_in[i];
        switch (in_sizes[i]) {
            case 4194304: x = p; break;
            case 16384:   w0 = p; break;
            case 128:     b0 = p; break;
            case 32768:   if (!w1) w1 = p; else w2 = p; break;
            case 256:     if (!b1) b1 = p; else b2 = p; break;
            default: break; // k, scale scalars
        }
    }
    float* out = (float*)d_out;

    cudaFuncSetAttribute(k_knn, cudaFuncAttributeMaxDynamicSharedMemorySize, SM_TOT);

    k_net  <<<dim3(32, 8),      256>>>(x, w0, b0);
    k_split<<<dim3(128, 4, 8),  256>>>();
    k_knn  <<<dim3(32, 8),      256, SM_TOT>>>();
    k_proj <<<dim3(32, 8, 2),   256>>>(w1, b1, w2, b2);
    k_edge <<<dim3(128, 8),     256>>>(out);
}

// round 6
// speedup vs baseline: 3.4511x; 3.4511x over previous
#include <cuda_runtime.h>
#include <cuda_fp16.h>
#include <float.h>
#include <stdint.h>

#define Bsz  8
#define Cdim 128
#define Ndim 4096
#define Odim 256
#define KNN  16

// ---------------- scratch (static device globals; no allocations) -------------
__device__ float g_net[Bsz * Cdim * Ndim];     // [b][c][n]      16 MB
__device__ float g_sq[Bsz * Ndim];             // [b][n]
__device__ int   g_idx[Bsz * Ndim * KNN];      // [b][n][k]       2 MB
__device__ float g_p1t[Bsz * Ndim * Odim];     // [b][n][o]      32 MB
__device__ float g_baset[Bsz * Ndim * Odim];   // [b][n][o]      32 MB
__device__ __half g_hi[Bsz * Ndim * Cdim];     // [b][n][c]       8 MB
__device__ __half g_lo[Bsz * Ndim * Cdim];     // [b][n][c]       8 MB

__device__ __forceinline__ uint32_t smem_u32(const void* p) {
    uint32_t a;
    asm("{ .reg .u64 t; cvta.to.shared.u64 t, %1; cvt.u32.u64 %0, t; }" : "=r"(a) : "l"(p));
    return a;
}
__device__ __forceinline__ void ldmx4(uint32_t* r, uint32_t addr) {
    asm volatile("ldmatrix.sync.aligned.m8n8.x4.shared.b16 {%0,%1,%2,%3}, [%4];"
        : "=r"(r[0]), "=r"(r[1]), "=r"(r[2]), "=r"(r[3]) : "r"(addr));
}
__device__ __forceinline__ void mma16816(float* c, const uint32_t* a,
                                         uint32_t b0, uint32_t b1) {
    asm volatile("mma.sync.aligned.m16n8k16.row.col.f32.f16.f16.f32 "
        "{%0,%1,%2,%3}, {%4,%5,%6,%7}, {%8,%9}, {%0,%1,%2,%3};"
        : "+f"(c[0]), "+f"(c[1]), "+f"(c[2]), "+f"(c[3])
        : "r"(a[0]), "r"(a[1]), "r"(a[2]), "r"(a[3]), "r"(b0), "r"(b1));
}

// ==============================================================================
// Kernel A: net = relu(w0 @ x + b0), fused sq[b][n] = sum_c net^2
// ==============================================================================
__global__ __launch_bounds__(256) void k_net(const float* __restrict__ x,
                                             const float* __restrict__ w0,
                                             const float* __restrict__ b0) {
    __shared__ float Ws[32][129];
    __shared__ float Ns[32][128];
    __shared__ float sqs[16][129];

    const int b  = blockIdx.y;
    const int n0 = blockIdx.x * 128;
    const int tid = threadIdx.x;
    const int tx = tid & 15;
    const int ty = tid >> 4;

    float acc[8][8];
    #pragma unroll
    for (int i = 0; i < 8; ++i)
        #pragma unroll
        for (int j = 0; j < 8; ++j) acc[i][j] = 0.f;

    for (int k0 = 0; k0 < 128; k0 += 32) {
        __syncthreads();
        #pragma unroll
        for (int i = 0; i < 16; ++i) {
            int idx = tid + i * 256;
            int cc = idx & 31, o = idx >> 5;
            Ws[cc][o] = w0[o * 128 + k0 + cc];
        }
        #pragma unroll
        for (int i = 0; i < 16; ++i) {
            int idx = tid + i * 256;
            int c = idx >> 7, n = idx & 127;
            Ns[c][n] = x[(b * 128 + k0 + c) * Ndim + n0 + n];
        }
        __syncthreads();
        #pragma unroll
        for (int kk = 0; kk < 32; ++kk) {
            float4 x0 = *(const float4*)&Ns[kk][tx * 8];
            float4 x1 = *(const float4*)&Ns[kk][tx * 8 + 4];
            float xr[8] = {x0.x, x0.y, x0.z, x0.w, x1.x, x1.y, x1.z, x1.w};
            #pragma unroll
            for (int i = 0; i < 8; ++i) {
                float wv = Ws[kk][ty * 8 + i];
                #pragma unroll
                for (int j = 0; j < 8; ++j) acc[i][j] += wv * xr[j];
            }
        }
    }

    float part[8];
    #pragma unroll
    for (int j = 0; j < 8; ++j) part[j] = 0.f;

    #pragma unroll
    for (int i = 0; i < 8; ++i) {
        int o = ty * 8 + i;
        float bv = __ldg(&b0[o]);
        float r[8];
        #pragma unroll
        for (int j = 0; j < 8; ++j) {
            r[j] = fmaxf(acc[i][j] + bv, 0.f);
            part[j] += r[j] * r[j];
        }
        int base = (b * 128 + o) * Ndim + n0 + tx * 8;
        float4 s0 = {r[0], r[1], r[2], r[3]};
        float4 s1 = {r[4], r[5], r[6], r[7]};
        *(float4*)&g_net[base]     = s0;
        *(float4*)&g_net[base + 4] = s1;
    }
    #pragma unroll
    for (int j = 0; j < 8; ++j) sqs[ty][tx * 8 + j] = part[j];
    __syncthreads();
    if (tid < 128) {
        float s = 0.f;
        #pragma unroll
        for (int r = 0; r < 16; ++r) s += sqs[r][tid];
        g_sq[b * Ndim + n0 + tid] = s;
    }
}

// ==============================================================================
// Kernel B: fp16 hi/lo split + transpose: g_net[b][c][n] -> g_hi/g_lo[b][n][c]
// ==============================================================================
__global__ __launch_bounds__(256) void k_split() {
    __shared__ float s[32][33];
    const int b  = blockIdx.z;
    const int c0 = blockIdx.y * 32;
    const int n0 = blockIdx.x * 32;
    const int tx = threadIdx.x & 31;
    const int ty = threadIdx.x >> 5;    // 0..7

    #pragma unroll
    for (int i = 0; i < 4; ++i) {
        int c = ty + i * 8;
        s[c][tx] = g_net[(b * Cdim + c0 + c) * Ndim + n0 + tx];
    }
    __syncthreads();
    #pragma unroll
    for (int i = 0; i < 4; ++i) {
        int nl = ty + i * 8;
        float v = s[tx][nl];
        __half hi = __float2half(v);
        __half lo = __float2half(v - __half2float(hi));
        int dst = (b * Ndim + n0 + nl) * Cdim + c0 + tx;
        g_hi[dst] = hi;
        g_lo[dst] = lo;
    }
}

// ==============================================================================
// Kernel C v5: kNN via mma.sync fp16 hi/lo gram + BRANCHLESS register top-17.
// grid (32, 8), 256 threads (8 warps). Warp w: q rows [w*16, w*16+16).
// ==============================================================================
#define PITCHB 272                     // 136 halves/row: conflict-free ldmatrix
#define TILEB  (128 * PITCHB)          // 34816 B per 128x128 fp16 tile
#define SM_QHI 0
#define SM_QLO TILEB
#define SM_MHI (2 * TILEB)
#define SM_MLO (3 * TILEB)
#define SM_KEY (4 * TILEB)             // 128 x 132 floats = 67584 B
#define SM_SQM (SM_KEY + 128 * 132 * 4)
#define SM_TOT (SM_SQM + 512)

__device__ __forceinline__ void load_tile16(char* smem, uint32_t dst,
                                            const __half* __restrict__ src) {
    for (int i = threadIdx.x; i < 2048; i += 256) {
        int row = i >> 4, c8 = (i & 15) * 8;
        uint4 v = *(const uint4*)(src + row * Cdim + c8);
        *(uint4*)(smem + dst + row * PITCHB + c8 * 2) = v;
    }
}

// Branchless sorted insert, all-static indices (registers only).
// Caller guarantees d < kd[16]. Stable on ties (earlier m stays ahead).
__device__ __forceinline__ void topk_insert_reg(float (&kd)[17], int (&ki)[17],
                                                float d, int m) {
    int r = 0;
    #pragma unroll
    for (int i = 0; i < 17; ++i) r += (kd[i] <= d) ? 1 : 0;
    #pragma unroll
    for (int j = 16; j > 0; --j) {
        bool sh = (j > r);
        kd[j] = sh ? kd[j - 1] : kd[j];
        ki[j] = sh ? ki[j - 1] : ki[j];
    }
    #pragma unroll
    for (int j = 0; j < 17; ++j)
        if (j == r) { kd[j] = d; ki[j] = m; }
}

__global__ __launch_bounds__(256) void k_knn() {
    extern __shared__ char smem[];
    const uint32_t sbase = smem_u32(smem);
    const int tid  = threadIdx.x;
    const int lane = tid & 31;
    const int wid  = tid >> 5;          // 0..7
    const int b    = blockIdx.y;
    const int n0   = blockIdx.x * 128;
    const int qbase = wid * 16;

    // Stage Q hi/lo once
    load_tile16(smem, SM_QHI, g_hi + (size_t)(b * Ndim + n0) * Cdim);
    load_tile16(smem, SM_QLO, g_lo + (size_t)(b * Ndim + n0) * Cdim);

    // ldmatrix base addresses (A: 16x16 row-major; B: [n][k] for col-major k x n)
    const uint32_t a_base = sbase + (qbase + (lane & 15)) * PITCHB + ((lane >> 4) << 4);
    const uint32_t b_base = sbase + ((lane & 7) + ((lane >> 4) << 3)) * PITCHB
                                  + (((lane >> 3) & 1) << 4);

    float* keysp = (float*)(smem + SM_KEY);
    const float* sqm = (const float*)(smem + SM_SQM);

    float kd[17]; int ki[17];
    #pragma unroll
    for (int i = 0; i < 17; ++i) { kd[i] = FLT_MAX; ki[i] = 0; }
    float worst = FLT_MAX;

    for (int mt = 0; mt < 32; ++mt) {
        const int m0 = mt * 128;
        __syncthreads();   // previous scan done; M tiles reusable
        load_tile16(smem, SM_MHI, g_hi + (size_t)(b * Ndim + m0) * Cdim);
        load_tile16(smem, SM_MLO, g_lo + (size_t)(b * Ndim + m0) * Cdim);
        if (tid < 128) ((float*)(smem + SM_SQM))[tid] = g_sq[b * Ndim + m0 + tid];
        __syncthreads();

        float c[16][4];
        #pragma unroll
        for (int t = 0; t < 16; ++t)
            #pragma unroll
            for (int e = 0; e < 4; ++e) c[t][e] = 0.f;

        #pragma unroll 1
        for (int pass = 0; pass < 3; ++pass) {
            const uint32_t abase = a_base + (pass == 2 ? SM_QLO : SM_QHI);
            const uint32_t bbase = b_base + (pass == 1 ? SM_MLO : SM_MHI);
            #pragma unroll
            for (int ks = 0; ks < 8; ++ks) {
                uint32_t ra[4];
                ldmx4(ra, abase + ks * 32);
                #pragma unroll
                for (int tp = 0; tp < 8; ++tp) {
                    uint32_t rb[4];
                    ldmx4(rb, bbase + tp * (16 * PITCHB) + ks * 32);
                    mma16816(c[2 * tp],     ra, rb[0], rb[1]);
                    mma16816(c[2 * tp + 1], ra, rb[2], rb[3]);
                }
            }
        }

        // keys[q][m] = sq[m] - 2*dot
        const int q0 = qbase + (lane >> 2);
        const int mo = (lane & 3) * 2;
        #pragma unroll
        for (int t = 0; t < 16; ++t) {
            int m = t * 8 + mo;
            float s0 = sqm[m], s1 = sqm[m + 1];
            *(float2*)&keysp[q0 * 132 + m] =
                make_float2(s0 - 2.f * c[t][0], s1 - 2.f * c[t][1]);
            *(float2*)&keysp[(q0 + 8) * 132 + m] =
                make_float2(s0 - 2.f * c[t][2], s1 - 2.f * c[t][3]);
        }
        __syncthreads();

        // streaming top-17 scan (threads 0..127, one query each) — register insert
        if (tid < 128) {
            const float* krow = keysp + tid * 132;
            #pragma unroll 4
            for (int m = 0; m < 128; ++m) {
                float kv = krow[m];
                if (kv < worst) { topk_insert_reg(kd, ki, kv, m0 + m); worst = kd[16]; }
            }
        }
    }

    if (tid < 128) {
        const int q = n0 + tid;
        #pragma unroll
        for (int t = 0; t < 16; ++t)
            g_idx[(b * Ndim + q) * KNN + t] = ki[t + 1];   // drop self (strict min)
    }
}

// ==============================================================================
// Kernel D v2: two independent 64-reg GEMMs selected by z&1:
//   which=0: p1   = w1@net                  -> g_p1t  [b][n][o]
//   which=1: base = (w2-w1)@net + (b1+b2)   -> g_baset[b][n][o]
// grid (32, 8, 4): z = (o_half << 1) | which. 256 threads: tx->o(8), ty->n(8).
// ==============================================================================
__global__ __launch_bounds__(256) void k_proj(const float* __restrict__ w1,
                                              const float* __restrict__ b1,
                                              const float* __restrict__ w2,
                                              const float* __restrict__ b2) {
    __shared__ float Wc[16][129];   // [c-chunk][o]
    __shared__ float Ns[16][128];   // [c-chunk][n]

    const int b     = blockIdx.y;
    const int n0    = blockIdx.x * 128;
    const int which = blockIdx.z & 1;
    const int oz    = (blockIdx.z >> 1) * 128;
    const int tid = threadIdx.x;
    const int tx = tid & 15;        // o group
    const int ty = tid >> 4;        // n group

    float a[8][8];                  // [j=n][i=o]
    #pragma unroll
    for (int j = 0; j < 8; ++j)
        #pragma unroll
        for (int i = 0; i < 8; ++i) a[j][i] = 0.f;

    for (int k0 = 0; k0 < 128; k0 += 16) {
        __syncthreads();
        #pragma unroll
        for (int i = 0; i < 8; ++i) {
            int idx = tid + i * 256;
            int cc = idx & 15, o = idx >> 4;
            float wv = w1[(oz + o) * 128 + k0 + cc];
            if (which) wv = w2[(oz + o) * 128 + k0 + cc] - wv;
            Wc[cc][o] = wv;
        }
        #pragma unroll
        for (int i = 0; i < 8; ++i) {
            int idx = tid + i * 256;
            int c = idx >> 7, n = idx & 127;
            Ns[c][n] = g_net[(b * 128 + k0 + c) * Ndim + n0 + n];
        }
        __syncthreads();
        #pragma unroll
        for (int kk = 0; kk < 16; ++kk) {
            float4 nv0 = *(const float4*)&Ns[kk][ty * 8];
            float4 nv1 = *(const float4*)&Ns[kk][ty * 8 + 4];
            float nr[8] = {nv0.x, nv0.y, nv0.z, nv0.w, nv1.x, nv1.y, nv1.z, nv1.w};
            float wr[8];
            #pragma unroll
            for (int i = 0; i < 8; ++i) wr[i] = Wc[kk][tx * 8 + i];
            #pragma unroll
            for (int j = 0; j < 8; ++j)
                #pragma unroll
                for (int i = 0; i < 8; ++i) a[j][i] += nr[j] * wr[i];
        }
    }

    float bb[8];
    #pragma unroll
    for (int i = 0; i < 8; ++i) {
        int o = oz + tx * 8 + i;
        bb[i] = which ? (__ldg(&b1[o]) + __ldg(&b2[o])) : 0.f;
    }
    float* dst = which ? g_baset : g_p1t;
    #pragma unroll
    for (int j = 0; j < 8; ++j) {
        int n = n0 + ty * 8 + j;
        int base = (b * Ndim + n) * Odim + oz + tx * 8;
        float4 v0 = {a[j][0] + bb[0], a[j][1] + bb[1], a[j][2] + bb[2], a[j][3] + bb[3]};
        float4 v1 = {a[j][4] + bb[4], a[j][5] + bb[5], a[j][6] + bb[6], a[j][7] + bb[7]};
        *(float4*)&dst[base]     = v0;
        *(float4*)&dst[base + 4] = v1;
    }
}

// ==============================================================================
// Kernel E: y[b,o,n] = relu(max_k (base[b,n,o] + p1t[b,idx[n,k],o]))
// ==============================================================================
__global__ __launch_bounds__(256) void k_edge(float* __restrict__ out) {
    __shared__ int   idxs[32][16];
    __shared__ float ys[32][257];

    const int b  = blockIdx.y;
    const int n0 = blockIdx.x * 32;
    const int tid = threadIdx.x;

    #pragma unroll
    for (int i = 0; i < 2; ++i) {
        int j = tid + i * 256;
        idxs[j >> 4][j & 15] = g_idx[(b * Ndim + n0 + (j >> 4)) * KNN + (j & 15)];
    }
    __syncthreads();

    #pragma unroll 1
    for (int nn = 0; nn < 32; ++nn) {
        float v = g_baset[(b * Ndim + n0 + nn) * Odim + tid];
        float acc = -FLT_MAX;
        #pragma unroll
        for (int t = 0; t < 16; ++t) {
            int m = idxs[nn][t];
            acc = fmaxf(acc, v + g_p1t[(b * Ndim + m) * Odim + tid]);
        }
        ys[nn][tid] = fmaxf(acc, 0.f);
    }
    __syncthreads();

    #pragma unroll
    for (int i = 0; i < 32; ++i) {
        int j = tid + i * 256;
        int o = j >> 5, n = j & 31;
        out[(b * Odim + o) * Ndim + n0 + n] = ys[n][o];
    }
}

// ==============================================================================
extern "C" void kernel_launch(void* const* d_in, const int* in_sizes, int n_in,
                              void* d_out, int out_size) {
    const float *x = 0, *w0 = 0, *b0 = 0, *w1 = 0, *b1 = 0, *w2 = 0, *b2 = 0;
    for (int i = 0; i < n_in; ++i) {
        const float* p = (const float*)d_in[i];
        switch (in_sizes[i]) {
            case 4194304: x = p; break;
            case 16384:   w0 = p; break;
            case 128:     b0 = p; break;
            case 32768:   if (!w1) w1 = p; else w2 = p; break;
            case 256:     if (!b1) b1 = p; else b2 = p; break;
            default: break; // k, scale scalars
        }
    }
    float* out = (float*)d_out;

    cudaFuncSetAttribute(k_knn, cudaFuncAttributeMaxDynamicSharedMemorySize, SM_TOT);

    k_net  <<<dim3(32, 8),      256>>>(x, w0, b0);
    k_split<<<dim3(128, 4, 8),  256>>>();
    k_knn  <<<dim3(32, 8),      256, SM_TOT>>>();
    k_proj <<<dim3(32, 8, 4),   256>>>(w1, b1, w2, b2);
    k_edge <<<dim3(128, 8),     256>>>(out);
}